// round 14
// baseline (speedup 1.0000x reference)
#include <cuda_runtime.h>
#include <cuda_bf16.h>
#include <math.h>

// Problem constants
#define kB 4
#define kS 1024
#define kD 1024
#define kN 16
#define kH 64
#define kBN 64  // kB * kN

// Scratch (device globals: allocation-free rule)
__device__ unsigned g_pb[(size_t)kBN * kS * kH / 2]; // p bf16 (8 MB)
__device__ unsigned g_tb[(size_t)kBN * kS * kH / 2]; // t bf16 (8 MB)
__device__ float g_xsum[kBN * kH];                   // 16 KB
__device__ float g_mf[(size_t)kBN * 72 * 64];        // fp32 M[bn][col][e]
__device__ unsigned g_xb[(size_t)kB * kS * kD / 2];  // x bf16 (8 MB)
__device__ unsigned g_winb[(size_t)kD * kD / 2];     // w_in bf16 (2 MB)
__device__ unsigned g_woutb[(size_t)kD * kD / 2];    // w_out bf16 (2 MB)
__device__ unsigned g_acb[(size_t)kB * kS * kD / 2]; // a_c bf16 (8 MB)
__device__ float g_inv[(size_t)kB * kS * kN];        // inv[s_glob][n]
__device__ float g_y[kBN * kD];                      // y[bn][d]

// ---------------------------------------------------------------------------
// MMA helpers
// ---------------------------------------------------------------------------
#define MMA_BF16(ac, a0, a1, a2, a3, b0, b1)                                   \
    asm volatile(                                                              \
        "mma.sync.aligned.m16n8k16.row.col.f32.bf16.bf16.f32 "                 \
        "{%0,%1,%2,%3}, {%4,%5,%6,%7}, {%8,%9}, {%0,%1,%2,%3};"                \
        : "+f"((ac)[0]), "+f"((ac)[1]), "+f"((ac)[2]), "+f"((ac)[3])           \
        : "r"(a0), "r"(a1), "r"(a2), "r"(a3), "r"(b0), "r"(b1))

// pack two f32 -> bf16x2 (lo = first arg), round-to-nearest (unbiased)
__device__ __forceinline__ unsigned pk(float lo, float hi) {
    unsigned r;
    asm("cvt.rn.bf16x2.f32 %0, %1, %2;" : "=r"(r) : "f"(hi), "f"(lo));
    return r;
}

__device__ __forceinline__ void cp16(unsigned saddr, const void* gaddr) {
    asm volatile("cp.async.cg.shared.global [%0], [%1], 16;"
                 :: "r"(saddr), "l"(gaddr));
}
#define CP_COMMIT() asm volatile("cp.async.commit_group;")
#define CP_WAIT(n)  asm volatile("cp.async.wait_group %0;" :: "n"(n))

// ---------------------------------------------------------------------------
// Fused f32 -> bf16 conversion for x, w_in, w_out in ONE launch.
// ---------------------------------------------------------------------------
__global__ void convert_inputs(const float* __restrict__ x,
                               const float* __restrict__ w_in,
                               const float* __restrict__ w_out,
                               unsigned* __restrict__ xb,
                               unsigned* __restrict__ winb,
                               unsigned* __restrict__ woutb)
{
    const int i = blockIdx.x * blockDim.x + threadIdx.x;
    const int NX = kB * kS * kD / 2, NW = kD * kD / 2;
    if (i < NX) {
        float2 v = ((const float2*)x)[i];
        xb[i] = pk(v.x, v.y);
    }
    if (i < NW) {
        float2 v = ((const float2*)w_in)[i];
        winb[i] = pk(v.x, v.y);
        float2 u = ((const float2*)w_out)[i];
        woutb[i] = pk(u.x, u.y);
    }
}

// ---------------------------------------------------------------------------
// Double-buffered BF16 NT GEMM: 128x128x64-per-stage, m16n8k16.
// MODE 0 (FUSE): writes p (bf16) + xsum; MODE 1 (BASE): out + mean path.
// ---------------------------------------------------------------------------
#define BSTG (128 * 36)
#define GB_SMEM_BYTES ((4 * BSTG + 16 * 132 + 128 * 16) * 4)

template <int MODE>
__global__ __launch_bounds__(256, 2) void gemm2b(
    const unsigned short* __restrict__ A, const unsigned short* __restrict__ B,
    const float* __restrict__ bias, void* __restrict__ Cv,
    float* __restrict__ xsum, const float* __restrict__ yg,
    const float* __restrict__ invg)
{
    extern __shared__ unsigned smw[];
    unsigned* sA = smw;                         // [2][128][36]
    unsigned* sB = smw + 2 * BSTG;              // [2][128][36]
    float* sxs  = (float*)(smw + 4 * BSTG);     // FUSE: [128]
    float* ys   = (float*)(smw + 4 * BSTG);     // BASE: [16][132]
    float* invs = ys + 16 * 132;                // BASE: [128][16]

    const int tid  = threadIdx.x;
    const int lane = tid & 31, wid = tid >> 5;
    const int warpRow = wid & 3, warpCol = wid >> 2;
    const int gid = lane >> 2, tig = lane & 3;
    const int row0 = blockIdx.y * 128, col0 = blockIdx.x * 128;

    if (MODE == 0) {
        if (tid < 128) sxs[tid] = 0.f;
    } else {
        const int b = row0 >> 10;
        for (int i = tid; i < 16 * 128; i += 256) {
            const int nn = i >> 7, c = i & 127;
            ys[nn * 132 + c] = yg[(b * 16 + nn) * kD + col0 + c];
        }
        for (int i = tid; i < 128 * 16; i += 256)
            invs[i] = invg[(size_t)(row0 + (i >> 4)) * 16 + (i & 15)];
    }

    const int lrow = tid >> 1;
    const int lsel = tid & 1;
    const unsigned short* Asrc = A + (size_t)(row0 + lrow) * kD + lsel * 32;
    const unsigned short* Bsrc = B + (size_t)(col0 + lrow) * kD + lsel * 32;
    const unsigned aB =
        (unsigned)__cvta_generic_to_shared(&sA[lrow * 36 + lsel * 16]);
    const unsigned bB =
        (unsigned)__cvta_generic_to_shared(&sB[lrow * 36 + lsel * 16]);

    float acc[2][8][4];
#pragma unroll
    for (int i = 0; i < 2; i++)
#pragma unroll
        for (int j = 0; j < 8; j++)
#pragma unroll
            for (int k = 0; k < 4; k++) acc[i][j][k] = 0.f;

#pragma unroll
    for (int j = 0; j < 4; j++) {
        cp16(aB + j * 16, Asrc + j * 8);
        cp16(bB + j * 16, Bsrc + j * 8);
    }
    CP_COMMIT();

    const int nIter = kD / 64;  // 16
    for (int it = 0; it < nIter; it++) {
        const int buf = it & 1;
        if (it + 1 < nIter) {
            const unsigned off = (buf ^ 1) * (BSTG * 4);
            const int k0 = (it + 1) * 64;
#pragma unroll
            for (int j = 0; j < 4; j++) {
                cp16(aB + off + j * 16, Asrc + k0 + j * 8);
                cp16(bB + off + j * 16, Bsrc + k0 + j * 8);
            }
            CP_COMMIT();
            CP_WAIT(1);
        } else {
            CP_WAIT(0);
        }
        __syncthreads();

        const unsigned* Ab = sA + buf * BSTG;
        const unsigned* Bb = sB + buf * BSTG;
#pragma unroll
        for (int j = 0; j < 4; j++) {
            unsigned af[2][4], bf2[8][2];
#pragma unroll
            for (int mt = 0; mt < 2; mt++) {
                const int m = warpRow * 32 + mt * 16 + gid;
                af[mt][0] = Ab[m * 36 + 8 * j + tig];
                af[mt][1] = Ab[(m + 8) * 36 + 8 * j + tig];
                af[mt][2] = Ab[m * 36 + 8 * j + tig + 4];
                af[mt][3] = Ab[(m + 8) * 36 + 8 * j + tig + 4];
            }
#pragma unroll
            for (int nt = 0; nt < 8; nt++) {
                const int n = warpCol * 64 + nt * 8 + gid;
                bf2[nt][0] = Bb[n * 36 + 8 * j + tig];
                bf2[nt][1] = Bb[n * 36 + 8 * j + tig + 4];
            }
#pragma unroll
            for (int mt = 0; mt < 2; mt++)
#pragma unroll
                for (int nt = 0; nt < 8; nt++)
                    MMA_BF16(acc[mt][nt], af[mt][0], af[mt][1], af[mt][2],
                             af[mt][3], bf2[nt][0], bf2[nt][1]);
        }
        __syncthreads();
    }

    if (MODE == 1) {
        float* C = (float*)Cv;
#pragma unroll
        for (int mt = 0; mt < 2; mt++) {
            const int rl = warpRow * 32 + mt * 16 + gid;
            float ia[16], ib[16];
#pragma unroll
            for (int q = 0; q < 4; q++) {
                *(float4*)&ia[q * 4] = *(float4*)&invs[rl * 16 + q * 4];
                *(float4*)&ib[q * 4] = *(float4*)&invs[(rl + 8) * 16 + q * 4];
            }
#pragma unroll
            for (int nt = 0; nt < 8; nt++) {
                const int cl = warpCol * 64 + nt * 8 + 2 * tig;
                float s00 = 0.f, s01 = 0.f, s10 = 0.f, s11 = 0.f;
#pragma unroll
                for (int n = 0; n < 16; n++) {
                    const float y0 = ys[n * 132 + cl];
                    const float y1 = ys[n * 132 + cl + 1];
                    s00 += ia[n] * y0; s01 += ia[n] * y1;
                    s10 += ib[n] * y0; s11 += ib[n] * y1;
                }
                const float bb0 = bias[col0 + cl], bb1 = bias[col0 + cl + 1];
                float2 v0, v1;
                v0.x = acc[mt][nt][0] + s00 + bb0;
                v0.y = acc[mt][nt][1] + s01 + bb1;
                v1.x = acc[mt][nt][2] + s10 + bb0;
                v1.y = acc[mt][nt][3] + s11 + bb1;
                *(float2*)(C + (size_t)(row0 + rl) * kD + col0 + cl)     = v0;
                *(float2*)(C + (size_t)(row0 + rl + 8) * kD + col0 + cl) = v1;
            }
        }
    } else {
        // FUSE epilogue: bias + per-head softmax; p written as bf16
        unsigned* Pb = (unsigned*)Cv;
        const int head = blockIdx.x * 2 + warpCol;
        const int b    = blockIdx.y >> 3;
        const int bn   = b * 16 + head;
#pragma unroll
        for (int mt = 0; mt < 2; mt++)
#pragma unroll
            for (int nt = 0; nt < 8; nt++) {
                const int col = col0 + warpCol * 64 + nt * 8 + 2 * tig;
                acc[mt][nt][0] += bias[col];
                acc[mt][nt][1] += bias[col + 1];
                acc[mt][nt][2] += bias[col];
                acc[mt][nt][3] += bias[col + 1];
            }
        float xacc[8][2];
#pragma unroll
        for (int nt = 0; nt < 8; nt++) { xacc[nt][0] = 0.f; xacc[nt][1] = 0.f; }

#pragma unroll
        for (int mt = 0; mt < 2; mt++) {
#pragma unroll
            for (int half = 0; half < 2; half++) {
                float mx = -1e30f;
#pragma unroll
                for (int nt = 0; nt < 8; nt++)
                    mx = fmaxf(mx, fmaxf(acc[mt][nt][half * 2],
                                         acc[mt][nt][half * 2 + 1]));
                mx = fmaxf(mx, __shfl_xor_sync(0xffffffffu, mx, 1));
                mx = fmaxf(mx, __shfl_xor_sync(0xffffffffu, mx, 2));
                float sum = 0.f;
#pragma unroll
                for (int nt = 0; nt < 8; nt++) {
                    float e0 = __expf(acc[mt][nt][half * 2]     - mx);
                    float e1 = __expf(acc[mt][nt][half * 2 + 1] - mx);
                    acc[mt][nt][half * 2]     = e0;
                    acc[mt][nt][half * 2 + 1] = e1;
                    sum += e0 + e1;
                }
                sum += __shfl_xor_sync(0xffffffffu, sum, 1);
                sum += __shfl_xor_sync(0xffffffffu, sum, 2);
                const float inv = 1.f / sum;
                const int s = (row0 & 1023) + warpRow * 32 + mt * 16 + gid + half * 8;
                unsigned* prow = Pb + ((size_t)bn * kS + s) * 32;
#pragma unroll
                for (int nt = 0; nt < 8; nt++) {
                    float p0 = acc[mt][nt][half * 2]     * inv;
                    float p1 = acc[mt][nt][half * 2 + 1] * inv;
                    prow[nt * 4 + tig] = pk(p0, p1);
                    xacc[nt][0] += p0;
                    xacc[nt][1] += p1;
                }
            }
        }
#pragma unroll
        for (int nt = 0; nt < 8; nt++) {
            atomicAdd(&sxs[warpCol * 64 + nt * 8 + 2 * tig],     xacc[nt][0]);
            atomicAdd(&sxs[warpCol * 64 + nt * 8 + 2 * tig + 1], xacc[nt][1]);
        }
        __syncthreads();
        if (tid < 128) {
            const int hh = tid & 63, hd = tid >> 6;
            atomicAdd(&xsum[(b * 16 + blockIdx.x * 2 + hd) * 64 + hh], sxs[tid]);
        }
    }
}

__global__ void zero_scratch(float* __restrict__ xsum, float* __restrict__ mf)
{
    const int i = blockIdx.x * blockDim.x + threadIdx.x;
    if (i < kBN * kH) xsum[i] = 0.f;
    if (i < kBN * 72 * 64) mf[i] = 0.f;
}

// ---------------------------------------------------------------------------
// compute_t6: t[bn][o][e] = sum_h W[o][n][e][h] * xsum[bn][h], bf16 out.
// 8 threads per e (part covers 8 h), 32 e per block -> ~56 regs, 4 blocks/SM.
// Grid: 4096 = 16 n x 128 oc x 2 e-half. Streaming W, xsum in regs.
// ---------------------------------------------------------------------------
__global__ __launch_bounds__(256, 4) void compute_t6(
    const float* __restrict__ W, const float* __restrict__ xsum,
    unsigned short* __restrict__ t)
{
    const int bid = blockIdx.x;
    const int n = bid & 15, oc = (bid >> 4) & 127, eh = bid >> 11;
    __shared__ float xs[4][64];
    {
        const int bb = threadIdx.x >> 6, hh = threadIdx.x & 63;
        xs[bb][hh] = xsum[(bb * 16 + n) * 64 + hh];
    }
    __syncthreads();
    const int el = threadIdx.x >> 3;        // 0..31
    const int e  = eh * 32 + el;
    const int part = threadIdx.x & 7;       // 8 h values each

    float4 xr[4][2];
#pragma unroll
    for (int bb = 0; bb < 4; bb++) {
        xr[bb][0] = *(const float4*)&xs[bb][part * 8];
        xr[bb][1] = *(const float4*)&xs[bb][part * 8 + 4];
    }

#pragma unroll
    for (int oi = 0; oi < 8; oi++) {
        const int o = oc * 8 + oi;
        const float4* w =
            (const float4*)(W + (((size_t)o * 16 + n) * 64 + e) * 64 + part * 8);
        const float4 w0 = w[0], w1 = w[1];
        float r[4];
#pragma unroll
        for (int bb = 0; bb < 4; bb++) {
            r[bb] = w0.x * xr[bb][0].x + w0.y * xr[bb][0].y
                  + w0.z * xr[bb][0].z + w0.w * xr[bb][0].w
                  + w1.x * xr[bb][1].x + w1.y * xr[bb][1].y
                  + w1.z * xr[bb][1].z + w1.w * xr[bb][1].w;
        }
#pragma unroll
        for (int bb = 0; bb < 4; bb++) {
            r[bb] += __shfl_xor_sync(0xffffffffu, r[bb], 1);
            r[bb] += __shfl_xor_sync(0xffffffffu, r[bb], 2);
            r[bb] += __shfl_xor_sync(0xffffffffu, r[bb], 4);
        }
        if (part < 4)
            t[(((size_t)(part * 16 + n)) * kS + o) * 64 + e] =
                __bfloat16_as_ushort(__float2bfloat16(r[part]));
    }
}

// ---------------------------------------------------------------------------
// calc_y: y[bn][d] = sum_h xsum[bn][h] * w_out[d][n*64+h] (fp32 exact).
// ---------------------------------------------------------------------------
__global__ __launch_bounds__(128) void calc_y(const float* __restrict__ xsum,
                                              const float* __restrict__ wout,
                                              float* __restrict__ y)
{
    const int n = blockIdx.x & 15, dc = blockIdx.x >> 4;
    __shared__ float xs[4][64];
    {
        int i = threadIdx.x;
        xs[i >> 6][i & 63] = xsum[((i >> 6) * 16 + n) * 64 + (i & 63)];
        i += 128;
        xs[i >> 6][i & 63] = xsum[((i >> 6) * 16 + n) * 64 + (i & 63)];
    }
    __syncthreads();
    const int d = dc * 128 + threadIdx.x;
    const float4* wp = (const float4*)(wout + (size_t)d * kD + n * 64);
    float a0 = 0.f, a1 = 0.f, a2 = 0.f, a3 = 0.f;
#pragma unroll
    for (int q = 0; q < 16; q++) {
        const float4 wv = wp[q];
        const float* x0 = &xs[0][q * 4];
        const float* x1 = &xs[1][q * 4];
        const float* x2 = &xs[2][q * 4];
        const float* x3 = &xs[3][q * 4];
        a0 += wv.x * x0[0] + wv.y * x0[1] + wv.z * x0[2] + wv.w * x0[3];
        a1 += wv.x * x1[0] + wv.y * x1[1] + wv.z * x1[2] + wv.w * x1[3];
        a2 += wv.x * x2[0] + wv.y * x2[1] + wv.z * x2[2] + wv.w * x2[3];
        a3 += wv.x * x3[0] + wv.y * x3[1] + wv.z * x3[2] + wv.w * x3[3];
    }
    y[(0 * 16 + n) * kD + d] = a0;
    y[(1 * 16 + n) * kD + d] = a1;
    y[(2 * 16 + n) * kD + d] = a2;
    y[(3 * 16 + n) * kD + d] = a3;
}

// ---------------------------------------------------------------------------
// gemm_m (split-K): partial M += t^T p over an o-chunk; tau via ones col.
// Sources are bf16 (t, p); transpose via PRMT. fp32 atomics out.
// Grid: (kBN, 8). 128 threads.
// ---------------------------------------------------------------------------
__global__ __launch_bounds__(128) void gemm_m(
    const unsigned* __restrict__ Tw, const unsigned* __restrict__ Pw,
    float* __restrict__ Mf)
{
    __shared__ unsigned As[64 * 36];
    __shared__ unsigned Bs[72 * 36];

    const int bn = blockIdx.x;
    const int o_base = blockIdx.y * 128;
    const int tid = threadIdx.x, lane = tid & 31, wid = tid >> 5;
    const int gid = lane >> 2, tig = lane & 3;
    const unsigned* Tp = Tw + (size_t)bn * kS * 32;
    const unsigned* Pp = Pw + (size_t)bn * kS * 32;

    for (int i = tid; i < 8 * 36; i += 128) {
        const int r = 64 + i / 36, w = i % 36;
        Bs[r * 36 + w] = (r == 64 && w < 32) ? 0x3F803F80u : 0u;
    }

    float acc[9][4];
#pragma unroll
    for (int j = 0; j < 9; j++)
#pragma unroll
        for (int k = 0; k < 4; k++) acc[j][k] = 0.f;

    const int op = tid & 31;
    const int cb = (tid >> 5) * 16;
    const int wb = cb >> 1;

#pragma unroll
    for (int oi = 0; oi < 2; oi++) {
        const int o0 = o_base + oi * 64;
        __syncthreads();
        {
            const unsigned* r0p = Tp + (size_t)(o0 + 2 * op) * 32 + wb;
            const unsigned* r1p = r0p + 32;
            uint4 u0 = *(const uint4*)(r0p);
            uint4 u1 = *(const uint4*)(r0p + 4);
            uint4 v0 = *(const uint4*)(r1p);
            uint4 v1 = *(const uint4*)(r1p + 4);
            const unsigned* ua = (const unsigned*)&u0;
            const unsigned* ub = (const unsigned*)&u1;
            const unsigned* va = (const unsigned*)&v0;
            const unsigned* vb = (const unsigned*)&v1;
#pragma unroll
            for (int q = 0; q < 4; q++) {
                As[(cb + 2 * q)     * 36 + op] = __byte_perm(ua[q], va[q], 0x5410);
                As[(cb + 2 * q + 1) * 36 + op] = __byte_perm(ua[q], va[q], 0x7632);
                As[(cb + 8 + 2 * q)     * 36 + op] = __byte_perm(ub[q], vb[q], 0x5410);
                As[(cb + 8 + 2 * q + 1) * 36 + op] = __byte_perm(ub[q], vb[q], 0x7632);
            }
        }
        {
            const unsigned* r0p = Pp + (size_t)(o0 + 2 * op) * 32 + wb;
            const unsigned* r1p = r0p + 32;
            uint4 u0 = *(const uint4*)(r0p);
            uint4 u1 = *(const uint4*)(r0p + 4);
            uint4 v0 = *(const uint4*)(r1p);
            uint4 v1 = *(const uint4*)(r1p + 4);
            const unsigned* ua = (const unsigned*)&u0;
            const unsigned* ub = (const unsigned*)&u1;
            const unsigned* va = (const unsigned*)&v0;
            const unsigned* vb = (const unsigned*)&v1;
#pragma unroll
            for (int q = 0; q < 4; q++) {
                Bs[(cb + 2 * q)     * 36 + op] = __byte_perm(ua[q], va[q], 0x5410);
                Bs[(cb + 2 * q + 1) * 36 + op] = __byte_perm(ua[q], va[q], 0x7632);
                Bs[(cb + 8 + 2 * q)     * 36 + op] = __byte_perm(ub[q], vb[q], 0x5410);
                Bs[(cb + 8 + 2 * q + 1) * 36 + op] = __byte_perm(ub[q], vb[q], 0x7632);
            }
        }
        __syncthreads();

        const int mrow = wid * 16 + gid;
#pragma unroll
        for (int j = 0; j < 4; j++) {
            unsigned a0 = As[mrow * 36 + 8 * j + tig];
            unsigned a1 = As[(mrow + 8) * 36 + 8 * j + tig];
            unsigned a2 = As[mrow * 36 + 8 * j + tig + 4];
            unsigned a3 = As[(mrow + 8) * 36 + 8 * j + tig + 4];
#pragma unroll
            for (int nt = 0; nt < 9; nt++) {
                unsigned b0 = Bs[(nt * 8 + gid) * 36 + 8 * j + tig];
                unsigned b1 = Bs[(nt * 8 + gid) * 36 + 8 * j + tig + 4];
                MMA_BF16(acc[nt], a0, a1, a2, a3, b0, b1);
            }
        }
    }

    float* mf = Mf + (size_t)bn * 72 * 64;
    const int mrow = wid * 16 + gid;
#pragma unroll
    for (int nt = 0; nt < 9; nt++) {
        const int col = nt * 8 + 2 * tig;
        if (col < 65) {
            atomicAdd(&mf[col * 64 + mrow],           acc[nt][0]);
            atomicAdd(&mf[col * 64 + mrow + 8],       acc[nt][2]);
            if (col + 1 < 65) {
                atomicAdd(&mf[(col + 1) * 64 + mrow],     acc[nt][1]);
                atomicAdd(&mf[(col + 1) * 64 + mrow + 8], acc[nt][3]);
            }
        }
    }
}

// ---------------------------------------------------------------------------
// gemm_apply: correction c = p_s @ M', denominator l; writes a_c bf16 + inv.
// ---------------------------------------------------------------------------
__global__ __launch_bounds__(256) void gemm_apply(
    const unsigned* __restrict__ Pw, const float* __restrict__ Mf,
    unsigned* __restrict__ ACb, float* __restrict__ Invg)
{
    __shared__ unsigned Ps[128 * 36];
    __shared__ unsigned Bs[72 * 36];

    const int bn = blockIdx.y;
    const int s0 = blockIdx.x * 128;
    const unsigned* Pp = Pw + (size_t)bn * kS * 32;
    const float* mf = Mf + (size_t)bn * 72 * 64;

    const int tid = threadIdx.x, lane = tid & 31, wid = tid >> 5;
    const int gid = lane >> 2, tig = lane & 3;
    const int mrow = wid * 16 + gid;
    const float ms = 1.f / 2048.f;

    for (int i = tid; i < 72 * 32; i += 256) {
        const int r = i >> 5, w = i & 31;
        float2 v = *(const float2*)(mf + r * 64 + 2 * w);
        Bs[r * 36 + w] = pk(v.x * ms, v.y * ms);
    }
    {
        const int r0 = tid >> 4, wc = (tid & 15) * 2;
#pragma unroll
        for (int pass = 0; pass < 8; pass++) {
            const int r = r0 + pass * 16;
            uint2 v = *(const uint2*)(Pp + (size_t)(s0 + r) * 32 + wc);
            *(uint2*)&Ps[r * 36 + wc] = v;
        }
    }
    __syncthreads();

    float acc[9][4];
#pragma unroll
    for (int j = 0; j < 9; j++)
#pragma unroll
        for (int k = 0; k < 4; k++) acc[j][k] = 0.f;

#pragma unroll
    for (int j = 0; j < 4; j++) {
        unsigned a0 = Ps[mrow * 36 + 8 * j + tig];
        unsigned a1 = Ps[(mrow + 8) * 36 + 8 * j + tig];
        unsigned a2 = Ps[mrow * 36 + 8 * j + tig + 4];
        unsigned a3 = Ps[(mrow + 8) * 36 + 8 * j + tig + 4];
#pragma unroll
        for (int nt = 0; nt < 9; nt++) {
            unsigned b0 = Bs[(nt * 8 + gid) * 36 + 8 * j + tig];
            unsigned b1 = Bs[(nt * 8 + gid) * 36 + 8 * j + tig + 4];
            MMA_BF16(acc[nt], a0, a1, a2, a3, b0, b1);
        }
    }

    const float tau0 = __shfl_sync(0xffffffffu, acc[8][0], lane & 28);
    const float tau1 = __shfl_sync(0xffffffffu, acc[8][2], lane & 28);
    const float inv0 = 1.f / (1024.f + tau0);
    const float inv1 = 1.f / (1024.f + tau1);

    const int b = bn >> 4, n = bn & 15;
    const size_t rglob = (size_t)(b * kS + s0 + mrow);
    unsigned* Cb = ACb + (rglob * kD + n * 64) / 2;
#pragma unroll
    for (int nt = 0; nt < 8; nt++) {
        Cb[nt * 4 + tig]          = pk(acc[nt][0] * inv0, acc[nt][1] * inv0);
        Cb[4 * kD + nt * 4 + tig] = pk(acc[nt][2] * inv1, acc[nt][3] * inv1);
    }
    if (tig == 0) {
        Invg[rglob * 16 + n]       = inv0;
        Invg[(rglob + 8) * 16 + n] = inv1;
    }
}

// ---------------------------------------------------------------------------
extern "C" void kernel_launch(void* const* d_in, const int* in_sizes, int n_in,
                              void* d_out, int out_size)
{
    (void)in_sizes; (void)n_in; (void)out_size;
    const float* x      = (const float*)d_in[0];
    const float* attn_w = (const float*)d_in[1];
    const float* w_in   = (const float*)d_in[2];
    const float* b_in   = (const float*)d_in[3];
    const float* w_out  = (const float*)d_in[4];
    const float* b_out  = (const float*)d_in[5];
    float* out = (float*)d_out;

    float *pxs, *pmf, *pinv, *py;
    unsigned *ppb, *ptb, *pxb, *pwinb, *pwoutb, *pacb;
    cudaGetSymbolAddress((void**)&ppb,   g_pb);
    cudaGetSymbolAddress((void**)&ptb,   g_tb);
    cudaGetSymbolAddress((void**)&pxs,   g_xsum);
    cudaGetSymbolAddress((void**)&pmf,   g_mf);
    cudaGetSymbolAddress((void**)&pinv,  g_inv);
    cudaGetSymbolAddress((void**)&py,    g_y);
    cudaGetSymbolAddress((void**)&pxb,   g_xb);
    cudaGetSymbolAddress((void**)&pwinb, g_winb);
    cudaGetSymbolAddress((void**)&pwoutb, g_woutb);
    cudaGetSymbolAddress((void**)&pacb,  g_acb);

    cudaFuncSetAttribute(gemm2b<0>, cudaFuncAttributeMaxDynamicSharedMemorySize,
                         GB_SMEM_BYTES);
    cudaFuncSetAttribute(gemm2b<1>, cudaFuncAttributeMaxDynamicSharedMemorySize,
                         GB_SMEM_BYTES);

    // 0) zero xsum + M scratch; convert x/w_in/w_out to bf16 (one launch)
    zero_scratch<<<(kBN * 72 * 64 + 255) / 256, 256>>>(pxs, pmf);
    convert_inputs<<<(kB * kS * kD / 2 + 255) / 256, 256>>>(
        x, w_in, w_out, pxb, pwinb, pwoutb);

    // 1+2) h = x @ w_in^T + b_in (bf16), fused softmax -> p (bf16), xsum
    gemm2b<0><<<dim3(kD / 128, (kB * kS) / 128), 256, GB_SMEM_BYTES>>>(
        (const unsigned short*)pxb, (const unsigned short*)pwinb,
        b_in, ppb, pxs, nullptr, nullptr);

    // 3) t = W . xsum (bf16 out, high-occupancy streaming)
    compute_t6<<<4096, 256>>>(attn_w, pxs, (unsigned short*)ptb);

    // 3b) y[bn][d] = xsum . w_out slice (fp32 exact mean path)
    calc_y<<<128, 128>>>(pxs, w_out, py);

    // 4) M = t^T @ p (+tau), split-K, fp32 atomics
    gemm_m<<<dim3(kBN, 8), 128>>>(ptb, ppb, pmf);

    // 5) correction a_c (bf16, inv-folded) + inv
    gemm_apply<<<dim3(kS / 128, kBN), 256>>>(ppb, pmf, pacb, pinv);

    // 6) out = a_c @ w_out^T (bf16) + sum_n inv*y (fp32) + b_out
    gemm2b<1><<<dim3(kD / 128, (kB * kS) / 128), 256, GB_SMEM_BYTES>>>(
        (const unsigned short*)pacb, (const unsigned short*)pwoutb,
        b_out, out, nullptr, py, pinv);
}

// round 15
// speedup vs baseline: 1.0640x; 1.0640x over previous
#include <cuda_runtime.h>
#include <cuda_bf16.h>
#include <math.h>

// Problem constants
#define kB 4
#define kS 1024
#define kD 1024
#define kN 16
#define kH 64
#define kBN 64  // kB * kN

// Scratch (device globals: allocation-free rule)
__device__ unsigned g_pb[(size_t)kBN * kS * kH / 2]; // p bf16 (8 MB)
__device__ unsigned g_tb[(size_t)kBN * kS * kH / 2]; // t bf16 (8 MB)
__device__ float g_xsum[kBN * kH];                   // 16 KB
__device__ float g_mf[(size_t)kBN * 72 * 64];        // fp32 M[bn][col][e]
__device__ unsigned g_xb[(size_t)kB * kS * kD / 2];  // x bf16 (8 MB)
__device__ unsigned g_winb[(size_t)kD * kD / 2];     // w_in bf16 (2 MB)
__device__ unsigned g_woutb[(size_t)kD * kD / 2];    // w_out bf16 (2 MB)
__device__ unsigned g_acb[(size_t)kB * kS * kD / 2]; // a_c bf16 (8 MB)
__device__ float g_inv[(size_t)kB * kS * kN];        // inv[s_glob][n]
__device__ float g_y[kBN * kD];                      // y[bn][d]

// ---------------------------------------------------------------------------
// MMA / ldmatrix helpers
// ---------------------------------------------------------------------------
#define MMA_BF16(ac, a0, a1, a2, a3, b0, b1)                                   \
    asm volatile(                                                              \
        "mma.sync.aligned.m16n8k16.row.col.f32.bf16.bf16.f32 "                 \
        "{%0,%1,%2,%3}, {%4,%5,%6,%7}, {%8,%9}, {%0,%1,%2,%3};"                \
        : "+f"((ac)[0]), "+f"((ac)[1]), "+f"((ac)[2]), "+f"((ac)[3])           \
        : "r"(a0), "r"(a1), "r"(a2), "r"(a3), "r"(b0), "r"(b1))

__device__ __forceinline__ void ldsm4(unsigned& r0, unsigned& r1,
                                      unsigned& r2, unsigned& r3,
                                      unsigned saddr) {
    asm volatile(
        "ldmatrix.sync.aligned.m8n8.x4.shared.b16 {%0,%1,%2,%3}, [%4];"
        : "=r"(r0), "=r"(r1), "=r"(r2), "=r"(r3) : "r"(saddr));
}

// pack two f32 -> bf16x2 (lo = first arg), round-to-nearest (unbiased)
__device__ __forceinline__ unsigned pk(float lo, float hi) {
    unsigned r;
    asm("cvt.rn.bf16x2.f32 %0, %1, %2;" : "=r"(r) : "f"(hi), "f"(lo));
    return r;
}

__device__ __forceinline__ void cp16(unsigned saddr, const void* gaddr) {
    asm volatile("cp.async.cg.shared.global [%0], [%1], 16;"
                 :: "r"(saddr), "l"(gaddr));
}
#define CP_COMMIT() asm volatile("cp.async.commit_group;")
#define CP_WAIT(n)  asm volatile("cp.async.wait_group %0;" :: "n"(n))

// ---------------------------------------------------------------------------
// Fused f32 -> bf16 conversion for x, w_in, w_out in ONE launch.
// ---------------------------------------------------------------------------
__global__ void convert_inputs(const float* __restrict__ x,
                               const float* __restrict__ w_in,
                               const float* __restrict__ w_out,
                               unsigned* __restrict__ xb,
                               unsigned* __restrict__ winb,
                               unsigned* __restrict__ woutb)
{
    const int i = blockIdx.x * blockDim.x + threadIdx.x;
    const int NX = kB * kS * kD / 2, NW = kD * kD / 2;
    if (i < NX) {
        float2 v = ((const float2*)x)[i];
        xb[i] = pk(v.x, v.y);
    }
    if (i < NW) {
        float2 v = ((const float2*)w_in)[i];
        winb[i] = pk(v.x, v.y);
        float2 u = ((const float2*)w_out)[i];
        woutb[i] = pk(u.x, u.y);
    }
}

// ---------------------------------------------------------------------------
// Double-buffered BF16 NT GEMM: 128x128x64-per-stage, m16n8k16, LDSM frags.
// MODE 0 (FUSE): writes p (bf16) + xsum; MODE 1 (BASE): out + mean path.
// ---------------------------------------------------------------------------
#define BSTG (128 * 36)
#define GB_SMEM_BYTES ((4 * BSTG + 16 * 132 + 128 * 16) * 4)

template <int MODE>
__global__ __launch_bounds__(256, 2) void gemm2b(
    const unsigned short* __restrict__ A, const unsigned short* __restrict__ B,
    const float* __restrict__ bias, void* __restrict__ Cv,
    float* __restrict__ xsum, const float* __restrict__ yg,
    const float* __restrict__ invg)
{
    extern __shared__ unsigned smw[];
    unsigned* sA = smw;                         // [2][128][36]
    unsigned* sB = smw + 2 * BSTG;              // [2][128][36]
    float* sxs  = (float*)(smw + 4 * BSTG);     // FUSE: [128]
    float* ys   = (float*)(smw + 4 * BSTG);     // BASE: [16][132]
    float* invs = ys + 16 * 132;                // BASE: [128][16]

    const int tid  = threadIdx.x;
    const int lane = tid & 31, wid = tid >> 5;
    const int warpRow = wid & 3, warpCol = wid >> 2;
    const int gid = lane >> 2, tig = lane & 3;
    const int row0 = blockIdx.y * 128, col0 = blockIdx.x * 128;

    if (MODE == 0) {
        if (tid < 128) sxs[tid] = 0.f;
    } else {
        const int b = row0 >> 10;
        for (int i = tid; i < 16 * 128; i += 256) {
            const int nn = i >> 7, c = i & 127;
            ys[nn * 132 + c] = yg[(b * 16 + nn) * kD + col0 + c];
        }
        for (int i = tid; i < 128 * 16; i += 256)
            invs[i] = invg[(size_t)(row0 + (i >> 4)) * 16 + (i & 15)];
    }

    const int lrow = tid >> 1;
    const int lsel = tid & 1;
    const unsigned short* Asrc = A + (size_t)(row0 + lrow) * kD + lsel * 32;
    const unsigned short* Bsrc = B + (size_t)(col0 + lrow) * kD + lsel * 32;
    const unsigned aB =
        (unsigned)__cvta_generic_to_shared(&sA[lrow * 36 + lsel * 16]);
    const unsigned bB =
        (unsigned)__cvta_generic_to_shared(&sB[lrow * 36 + lsel * 16]);

    // ldmatrix lane-dependent address offsets (bytes)
    // A: row = warpRow*32 + mt*16 + (lane&15); col-half = (lane>>4)*8 bf16
    const int la  = lane & 15, lka = (lane >> 4) * 4;  // col off in words
    const unsigned sAbase = (unsigned)__cvta_generic_to_shared(sA);
    const unsigned sBbase = (unsigned)__cvta_generic_to_shared(sB);
    const unsigned aoff0 =
        ((warpRow * 32 + la) * 36 + lka) * 4;
    const unsigned aoff1 =
        ((warpRow * 32 + 16 + la) * 36 + lka) * 4;
    // B: for pair a: rows n = warpCol*64 + 16a + (lane&7) + ((lane>>4)&1)*8,
    //    col-half = ((lane>>3)&1)*8 bf16
    const int lrB = (lane & 7) + ((lane >> 4) & 1) * 8;
    const int lcB = ((lane >> 3) & 1) * 4;  // words
    unsigned boff[4];
#pragma unroll
    for (int a = 0; a < 4; a++)
        boff[a] = ((warpCol * 64 + 16 * a + lrB) * 36 + lcB) * 4;

    float acc[2][8][4];
#pragma unroll
    for (int i = 0; i < 2; i++)
#pragma unroll
        for (int j = 0; j < 8; j++)
#pragma unroll
            for (int k = 0; k < 4; k++) acc[i][j][k] = 0.f;

#pragma unroll
    for (int j = 0; j < 4; j++) {
        cp16(aB + j * 16, Asrc + j * 8);
        cp16(bB + j * 16, Bsrc + j * 8);
    }
    CP_COMMIT();

    const int nIter = kD / 64;  // 16
    for (int it = 0; it < nIter; it++) {
        const int buf = it & 1;
        if (it + 1 < nIter) {
            const unsigned off = (buf ^ 1) * (BSTG * 4);
            const int k0 = (it + 1) * 64;
#pragma unroll
            for (int j = 0; j < 4; j++) {
                cp16(aB + off + j * 16, Asrc + k0 + j * 8);
                cp16(bB + off + j * 16, Bsrc + k0 + j * 8);
            }
            CP_COMMIT();
            CP_WAIT(1);
        } else {
            CP_WAIT(0);
        }
        __syncthreads();

        const unsigned abuf = sAbase + buf * (BSTG * 4);
        const unsigned bbuf = sBbase + buf * (BSTG * 4);
#pragma unroll
        for (int j = 0; j < 4; j++) {
            unsigned af[2][4], bf2[8][2];
            ldsm4(af[0][0], af[0][1], af[0][2], af[0][3],
                  abuf + aoff0 + j * 32);
            ldsm4(af[1][0], af[1][1], af[1][2], af[1][3],
                  abuf + aoff1 + j * 32);
#pragma unroll
            for (int a = 0; a < 4; a++)
                ldsm4(bf2[2 * a][0], bf2[2 * a][1],
                      bf2[2 * a + 1][0], bf2[2 * a + 1][1],
                      bbuf + boff[a] + j * 32);
#pragma unroll
            for (int mt = 0; mt < 2; mt++)
#pragma unroll
                for (int nt = 0; nt < 8; nt++)
                    MMA_BF16(acc[mt][nt], af[mt][0], af[mt][1], af[mt][2],
                             af[mt][3], bf2[nt][0], bf2[nt][1]);
        }
        __syncthreads();
    }

    if (MODE == 1) {
        float* C = (float*)Cv;
#pragma unroll
        for (int mt = 0; mt < 2; mt++) {
            const int rl = warpRow * 32 + mt * 16 + gid;
            float ia[16], ib[16];
#pragma unroll
            for (int q = 0; q < 4; q++) {
                *(float4*)&ia[q * 4] = *(float4*)&invs[rl * 16 + q * 4];
                *(float4*)&ib[q * 4] = *(float4*)&invs[(rl + 8) * 16 + q * 4];
            }
#pragma unroll
            for (int nt = 0; nt < 8; nt++) {
                const int cl = warpCol * 64 + nt * 8 + 2 * tig;
                float s00 = 0.f, s01 = 0.f, s10 = 0.f, s11 = 0.f;
#pragma unroll
                for (int n = 0; n < 16; n++) {
                    const float y0 = ys[n * 132 + cl];
                    const float y1 = ys[n * 132 + cl + 1];
                    s00 += ia[n] * y0; s01 += ia[n] * y1;
                    s10 += ib[n] * y0; s11 += ib[n] * y1;
                }
                const float bb0 = bias[col0 + cl], bb1 = bias[col0 + cl + 1];
                float2 v0, v1;
                v0.x = acc[mt][nt][0] + s00 + bb0;
                v0.y = acc[mt][nt][1] + s01 + bb1;
                v1.x = acc[mt][nt][2] + s10 + bb0;
                v1.y = acc[mt][nt][3] + s11 + bb1;
                *(float2*)(C + (size_t)(row0 + rl) * kD + col0 + cl)     = v0;
                *(float2*)(C + (size_t)(row0 + rl + 8) * kD + col0 + cl) = v1;
            }
        }
    } else {
        // FUSE epilogue: bias + per-head softmax; p written as bf16
        unsigned* Pb = (unsigned*)Cv;
        const int head = blockIdx.x * 2 + warpCol;
        const int b    = blockIdx.y >> 3;
        const int bn   = b * 16 + head;
#pragma unroll
        for (int mt = 0; mt < 2; mt++)
#pragma unroll
            for (int nt = 0; nt < 8; nt++) {
                const int col = col0 + warpCol * 64 + nt * 8 + 2 * tig;
                acc[mt][nt][0] += bias[col];
                acc[mt][nt][1] += bias[col + 1];
                acc[mt][nt][2] += bias[col];
                acc[mt][nt][3] += bias[col + 1];
            }
        float xacc[8][2];
#pragma unroll
        for (int nt = 0; nt < 8; nt++) { xacc[nt][0] = 0.f; xacc[nt][1] = 0.f; }

#pragma unroll
        for (int mt = 0; mt < 2; mt++) {
#pragma unroll
            for (int half = 0; half < 2; half++) {
                float mx = -1e30f;
#pragma unroll
                for (int nt = 0; nt < 8; nt++)
                    mx = fmaxf(mx, fmaxf(acc[mt][nt][half * 2],
                                         acc[mt][nt][half * 2 + 1]));
                mx = fmaxf(mx, __shfl_xor_sync(0xffffffffu, mx, 1));
                mx = fmaxf(mx, __shfl_xor_sync(0xffffffffu, mx, 2));
                float sum = 0.f;
#pragma unroll
                for (int nt = 0; nt < 8; nt++) {
                    float e0 = __expf(acc[mt][nt][half * 2]     - mx);
                    float e1 = __expf(acc[mt][nt][half * 2 + 1] - mx);
                    acc[mt][nt][half * 2]     = e0;
                    acc[mt][nt][half * 2 + 1] = e1;
                    sum += e0 + e1;
                }
                sum += __shfl_xor_sync(0xffffffffu, sum, 1);
                sum += __shfl_xor_sync(0xffffffffu, sum, 2);
                const float inv = 1.f / sum;
                const int s = (row0 & 1023) + warpRow * 32 + mt * 16 + gid + half * 8;
                unsigned* prow = Pb + ((size_t)bn * kS + s) * 32;
#pragma unroll
                for (int nt = 0; nt < 8; nt++) {
                    float p0 = acc[mt][nt][half * 2]     * inv;
                    float p1 = acc[mt][nt][half * 2 + 1] * inv;
                    prow[nt * 4 + tig] = pk(p0, p1);
                    xacc[nt][0] += p0;
                    xacc[nt][1] += p1;
                }
            }
        }
#pragma unroll
        for (int nt = 0; nt < 8; nt++) {
            atomicAdd(&sxs[warpCol * 64 + nt * 8 + 2 * tig],     xacc[nt][0]);
            atomicAdd(&sxs[warpCol * 64 + nt * 8 + 2 * tig + 1], xacc[nt][1]);
        }
        __syncthreads();
        if (tid < 128) {
            const int hh = tid & 63, hd = tid >> 6;
            atomicAdd(&xsum[(b * 16 + blockIdx.x * 2 + hd) * 64 + hh], sxs[tid]);
        }
    }
}

__global__ void zero_scratch(float* __restrict__ xsum, float* __restrict__ mf)
{
    const int i = blockIdx.x * blockDim.x + threadIdx.x;
    if (i < kBN * kH) xsum[i] = 0.f;
    if (i < kBN * 72 * 64) mf[i] = 0.f;
}

// ---------------------------------------------------------------------------
// compute_t4b: t[bn][o][e] = sum_h W[o][n][e][h] * xsum[bn][h], bf16 out.
// Block per (n, 8 o's). xsum in registers; direct streaming W reads
// (8-deep unroll keeps ~32 independent LDG.128 in flight). Grid: 2048.
// ---------------------------------------------------------------------------
__global__ __launch_bounds__(256, 2) void compute_t4b(
    const float* __restrict__ W, const float* __restrict__ xsum,
    unsigned short* __restrict__ t)
{
    const int n = blockIdx.x & 15, oc = blockIdx.x >> 4;
    __shared__ float xs[4][64];
    {
        const int bb = threadIdx.x >> 6, hh = threadIdx.x & 63;
        xs[bb][hh] = xsum[(bb * 16 + n) * 64 + hh];
    }
    __syncthreads();
    const int e = threadIdx.x >> 2, part = threadIdx.x & 3;
    float4 xr[4][4];
#pragma unroll
    for (int bb = 0; bb < 4; bb++)
#pragma unroll
        for (int j = 0; j < 4; j++)
            xr[bb][j] = *(const float4*)&xs[bb][part * 16 + j * 4];

#pragma unroll
    for (int oi = 0; oi < 8; oi++) {
        const int o = oc * 8 + oi;
        const float4* w =
            (const float4*)(W + (((size_t)o * 16 + n) * 64 + e) * 64 + part * 16);
        const float4 w0 = w[0], w1 = w[1], w2 = w[2], w3 = w[3];
        float r[4];
#pragma unroll
        for (int bb = 0; bb < 4; bb++) {
            r[bb] = w0.x * xr[bb][0].x + w0.y * xr[bb][0].y
                  + w0.z * xr[bb][0].z + w0.w * xr[bb][0].w
                  + w1.x * xr[bb][1].x + w1.y * xr[bb][1].y
                  + w1.z * xr[bb][1].z + w1.w * xr[bb][1].w
                  + w2.x * xr[bb][2].x + w2.y * xr[bb][2].y
                  + w2.z * xr[bb][2].z + w2.w * xr[bb][2].w
                  + w3.x * xr[bb][3].x + w3.y * xr[bb][3].y
                  + w3.z * xr[bb][3].z + w3.w * xr[bb][3].w;
        }
#pragma unroll
        for (int bb = 0; bb < 4; bb++) {
            r[bb] += __shfl_xor_sync(0xffffffffu, r[bb], 1);
            r[bb] += __shfl_xor_sync(0xffffffffu, r[bb], 2);
        }
        t[(((size_t)(part * 16 + n)) * kS + o) * 64 + e] =
            __bfloat16_as_ushort(__float2bfloat16(r[part]));
    }
}

// ---------------------------------------------------------------------------
// calc_y: y[bn][d] = sum_h xsum[bn][h] * w_out[d][n*64+h] (fp32 exact).
// ---------------------------------------------------------------------------
__global__ __launch_bounds__(128) void calc_y(const float* __restrict__ xsum,
                                              const float* __restrict__ wout,
                                              float* __restrict__ y)
{
    const int n = blockIdx.x & 15, dc = blockIdx.x >> 4;
    __shared__ float xs[4][64];
    {
        int i = threadIdx.x;
        xs[i >> 6][i & 63] = xsum[((i >> 6) * 16 + n) * 64 + (i & 63)];
        i += 128;
        xs[i >> 6][i & 63] = xsum[((i >> 6) * 16 + n) * 64 + (i & 63)];
    }
    __syncthreads();
    const int d = dc * 128 + threadIdx.x;
    const float4* wp = (const float4*)(wout + (size_t)d * kD + n * 64);
    float a0 = 0.f, a1 = 0.f, a2 = 0.f, a3 = 0.f;
#pragma unroll
    for (int q = 0; q < 16; q++) {
        const float4 wv = wp[q];
        const float* x0 = &xs[0][q * 4];
        const float* x1 = &xs[1][q * 4];
        const float* x2 = &xs[2][q * 4];
        const float* x3 = &xs[3][q * 4];
        a0 += wv.x * x0[0] + wv.y * x0[1] + wv.z * x0[2] + wv.w * x0[3];
        a1 += wv.x * x1[0] + wv.y * x1[1] + wv.z * x1[2] + wv.w * x1[3];
        a2 += wv.x * x2[0] + wv.y * x2[1] + wv.z * x2[2] + wv.w * x2[3];
        a3 += wv.x * x3[0] + wv.y * x3[1] + wv.z * x3[2] + wv.w * x3[3];
    }
    y[(0 * 16 + n) * kD + d] = a0;
    y[(1 * 16 + n) * kD + d] = a1;
    y[(2 * 16 + n) * kD + d] = a2;
    y[(3 * 16 + n) * kD + d] = a3;
}

// ---------------------------------------------------------------------------
// gemm_m (split-K): partial M += t^T p over an o-chunk; tau via ones col.
// Sources are bf16 (t, p); transpose via PRMT. fp32 atomics out.
// Grid: (kBN, 8). 128 threads.
// ---------------------------------------------------------------------------
__global__ __launch_bounds__(128) void gemm_m(
    const unsigned* __restrict__ Tw, const unsigned* __restrict__ Pw,
    float* __restrict__ Mf)
{
    __shared__ unsigned As[64 * 36];
    __shared__ unsigned Bs[72 * 36];

    const int bn = blockIdx.x;
    const int o_base = blockIdx.y * 128;
    const int tid = threadIdx.x, lane = tid & 31, wid = tid >> 5;
    const int gid = lane >> 2, tig = lane & 3;
    const unsigned* Tp = Tw + (size_t)bn * kS * 32;
    const unsigned* Pp = Pw + (size_t)bn * kS * 32;

    for (int i = tid; i < 8 * 36; i += 128) {
        const int r = 64 + i / 36, w = i % 36;
        Bs[r * 36 + w] = (r == 64 && w < 32) ? 0x3F803F80u : 0u;
    }

    float acc[9][4];
#pragma unroll
    for (int j = 0; j < 9; j++)
#pragma unroll
        for (int k = 0; k < 4; k++) acc[j][k] = 0.f;

    const int op = tid & 31;
    const int cb = (tid >> 5) * 16;
    const int wb = cb >> 1;

#pragma unroll
    for (int oi = 0; oi < 2; oi++) {
        const int o0 = o_base + oi * 64;
        __syncthreads();
        {
            const unsigned* r0p = Tp + (size_t)(o0 + 2 * op) * 32 + wb;
            const unsigned* r1p = r0p + 32;
            uint4 u0 = *(const uint4*)(r0p);
            uint4 u1 = *(const uint4*)(r0p + 4);
            uint4 v0 = *(const uint4*)(r1p);
            uint4 v1 = *(const uint4*)(r1p + 4);
            const unsigned* ua = (const unsigned*)&u0;
            const unsigned* ub = (const unsigned*)&u1;
            const unsigned* va = (const unsigned*)&v0;
            const unsigned* vb = (const unsigned*)&v1;
#pragma unroll
            for (int q = 0; q < 4; q++) {
                As[(cb + 2 * q)     * 36 + op] = __byte_perm(ua[q], va[q], 0x5410);
                As[(cb + 2 * q + 1) * 36 + op] = __byte_perm(ua[q], va[q], 0x7632);
                As[(cb + 8 + 2 * q)     * 36 + op] = __byte_perm(ub[q], vb[q], 0x5410);
                As[(cb + 8 + 2 * q + 1) * 36 + op] = __byte_perm(ub[q], vb[q], 0x7632);
            }
        }
        {
            const unsigned* r0p = Pp + (size_t)(o0 + 2 * op) * 32 + wb;
            const unsigned* r1p = r0p + 32;
            uint4 u0 = *(const uint4*)(r0p);
            uint4 u1 = *(const uint4*)(r0p + 4);
            uint4 v0 = *(const uint4*)(r1p);
            uint4 v1 = *(const uint4*)(r1p + 4);
            const unsigned* ua = (const unsigned*)&u0;
            const unsigned* ub = (const unsigned*)&u1;
            const unsigned* va = (const unsigned*)&v0;
            const unsigned* vb = (const unsigned*)&v1;
#pragma unroll
            for (int q = 0; q < 4; q++) {
                Bs[(cb + 2 * q)     * 36 + op] = __byte_perm(ua[q], va[q], 0x5410);
                Bs[(cb + 2 * q + 1) * 36 + op] = __byte_perm(ua[q], va[q], 0x7632);
                Bs[(cb + 8 + 2 * q)     * 36 + op] = __byte_perm(ub[q], vb[q], 0x5410);
                Bs[(cb + 8 + 2 * q + 1) * 36 + op] = __byte_perm(ub[q], vb[q], 0x7632);
            }
        }
        __syncthreads();

        const int mrow = wid * 16 + gid;
#pragma unroll
        for (int j = 0; j < 4; j++) {
            unsigned a0 = As[mrow * 36 + 8 * j + tig];
            unsigned a1 = As[(mrow + 8) * 36 + 8 * j + tig];
            unsigned a2 = As[mrow * 36 + 8 * j + tig + 4];
            unsigned a3 = As[(mrow + 8) * 36 + 8 * j + tig + 4];
#pragma unroll
            for (int nt = 0; nt < 9; nt++) {
                unsigned b0 = Bs[(nt * 8 + gid) * 36 + 8 * j + tig];
                unsigned b1 = Bs[(nt * 8 + gid) * 36 + 8 * j + tig + 4];
                MMA_BF16(acc[nt], a0, a1, a2, a3, b0, b1);
            }
        }
    }

    float* mf = Mf + (size_t)bn * 72 * 64;
    const int mrow = wid * 16 + gid;
#pragma unroll
    for (int nt = 0; nt < 9; nt++) {
        const int col = nt * 8 + 2 * tig;
        if (col < 65) {
            atomicAdd(&mf[col * 64 + mrow],           acc[nt][0]);
            atomicAdd(&mf[col * 64 + mrow + 8],       acc[nt][2]);
            if (col + 1 < 65) {
                atomicAdd(&mf[(col + 1) * 64 + mrow],     acc[nt][1]);
                atomicAdd(&mf[(col + 1) * 64 + mrow + 8], acc[nt][3]);
            }
        }
    }
}

// ---------------------------------------------------------------------------
// gemm_apply: correction c = p_s @ M', denominator l; writes a_c bf16 + inv.
// ---------------------------------------------------------------------------
__global__ __launch_bounds__(256) void gemm_apply(
    const unsigned* __restrict__ Pw, const float* __restrict__ Mf,
    unsigned* __restrict__ ACb, float* __restrict__ Invg)
{
    __shared__ unsigned Ps[128 * 36];
    __shared__ unsigned Bs[72 * 36];

    const int bn = blockIdx.y;
    const int s0 = blockIdx.x * 128;
    const unsigned* Pp = Pw + (size_t)bn * kS * 32;
    const float* mf = Mf + (size_t)bn * 72 * 64;

    const int tid = threadIdx.x, lane = tid & 31, wid = tid >> 5;
    const int gid = lane >> 2, tig = lane & 3;
    const int mrow = wid * 16 + gid;
    const float ms = 1.f / 2048.f;

    for (int i = tid; i < 72 * 32; i += 256) {
        const int r = i >> 5, w = i & 31;
        float2 v = *(const float2*)(mf + r * 64 + 2 * w);
        Bs[r * 36 + w] = pk(v.x * ms, v.y * ms);
    }
    {
        const int r0 = tid >> 4, wc = (tid & 15) * 2;
#pragma unroll
        for (int pass = 0; pass < 8; pass++) {
            const int r = r0 + pass * 16;
            uint2 v = *(const uint2*)(Pp + (size_t)(s0 + r) * 32 + wc);
            *(uint2*)&Ps[r * 36 + wc] = v;
        }
    }
    __syncthreads();

    float acc[9][4];
#pragma unroll
    for (int j = 0; j < 9; j++)
#pragma unroll
        for (int k = 0; k < 4; k++) acc[j][k] = 0.f;

#pragma unroll
    for (int j = 0; j < 4; j++) {
        unsigned a0 = Ps[mrow * 36 + 8 * j + tig];
        unsigned a1 = Ps[(mrow + 8) * 36 + 8 * j + tig];
        unsigned a2 = Ps[mrow * 36 + 8 * j + tig + 4];
        unsigned a3 = Ps[(mrow + 8) * 36 + 8 * j + tig + 4];
#pragma unroll
        for (int nt = 0; nt < 9; nt++) {
            unsigned b0 = Bs[(nt * 8 + gid) * 36 + 8 * j + tig];
            unsigned b1 = Bs[(nt * 8 + gid) * 36 + 8 * j + tig + 4];
            MMA_BF16(acc[nt], a0, a1, a2, a3, b0, b1);
        }
    }

    const float tau0 = __shfl_sync(0xffffffffu, acc[8][0], lane & 28);
    const float tau1 = __shfl_sync(0xffffffffu, acc[8][2], lane & 28);
    const float inv0 = 1.f / (1024.f + tau0);
    const float inv1 = 1.f / (1024.f + tau1);

    const int b = bn >> 4, n = bn & 15;
    const size_t rglob = (size_t)(b * kS + s0 + mrow);
    unsigned* Cb = ACb + (rglob * kD + n * 64) / 2;
#pragma unroll
    for (int nt = 0; nt < 8; nt++) {
        Cb[nt * 4 + tig]          = pk(acc[nt][0] * inv0, acc[nt][1] * inv0);
        Cb[4 * kD + nt * 4 + tig] = pk(acc[nt][2] * inv1, acc[nt][3] * inv1);
    }
    if (tig == 0) {
        Invg[rglob * 16 + n]       = inv0;
        Invg[(rglob + 8) * 16 + n] = inv1;
    }
}

// ---------------------------------------------------------------------------
extern "C" void kernel_launch(void* const* d_in, const int* in_sizes, int n_in,
                              void* d_out, int out_size)
{
    (void)in_sizes; (void)n_in; (void)out_size;
    const float* x      = (const float*)d_in[0];
    const float* attn_w = (const float*)d_in[1];
    const float* w_in   = (const float*)d_in[2];
    const float* b_in   = (const float*)d_in[3];
    const float* w_out  = (const float*)d_in[4];
    const float* b_out  = (const float*)d_in[5];
    float* out = (float*)d_out;

    float *pxs, *pmf, *pinv, *py;
    unsigned *ppb, *ptb, *pxb, *pwinb, *pwoutb, *pacb;
    cudaGetSymbolAddress((void**)&ppb,   g_pb);
    cudaGetSymbolAddress((void**)&ptb,   g_tb);
    cudaGetSymbolAddress((void**)&pxs,   g_xsum);
    cudaGetSymbolAddress((void**)&pmf,   g_mf);
    cudaGetSymbolAddress((void**)&pinv,  g_inv);
    cudaGetSymbolAddress((void**)&py,    g_y);
    cudaGetSymbolAddress((void**)&pxb,   g_xb);
    cudaGetSymbolAddress((void**)&pwinb, g_winb);
    cudaGetSymbolAddress((void**)&pwoutb, g_woutb);
    cudaGetSymbolAddress((void**)&pacb,  g_acb);

    cudaFuncSetAttribute(gemm2b<0>, cudaFuncAttributeMaxDynamicSharedMemorySize,
                         GB_SMEM_BYTES);
    cudaFuncSetAttribute(gemm2b<1>, cudaFuncAttributeMaxDynamicSharedMemorySize,
                         GB_SMEM_BYTES);

    // 0) zero xsum + M scratch; convert x/w_in/w_out to bf16 (one launch)
    zero_scratch<<<(kBN * 72 * 64 + 255) / 256, 256>>>(pxs, pmf);
    convert_inputs<<<(kB * kS * kD / 2 + 255) / 256, 256>>>(
        x, w_in, w_out, pxb, pwinb, pwoutb);

    // 1+2) h = x @ w_in^T + b_in (bf16, LDSM), fused softmax -> p, xsum
    gemm2b<0><<<dim3(kD / 128, (kB * kS) / 128), 256, GB_SMEM_BYTES>>>(
        (const unsigned short*)pxb, (const unsigned short*)pwinb,
        b_in, ppb, pxs, nullptr, nullptr);

    // 3) t = W . xsum (bf16 out, high-MLP streaming — R13 version)
    compute_t4b<<<2048, 256>>>(attn_w, pxs, (unsigned short*)ptb);

    // 3b) y[bn][d] = xsum . w_out slice (fp32 exact mean path)
    calc_y<<<128, 128>>>(pxs, w_out, py);

    // 4) M = t^T @ p (+tau), split-K, fp32 atomics
    gemm_m<<<dim3(kBN, 8), 128>>>(ptb, ppb, pmf);

    // 5) correction a_c (bf16, inv-folded) + inv
    gemm_apply<<<dim3(kS / 128, kBN), 256>>>(ppb, pmf, pacb, pinv);

    // 6) out = a_c @ w_out^T (bf16, LDSM) + sum_n inv*y (fp32) + b_out
    gemm2b<1><<<dim3(kD / 128, (kB * kS) / 128), 256, GB_SMEM_BYTES>>>(
        (const unsigned short*)pacb, (const unsigned short*)pwoutb,
        b_out, out, nullptr, py, pinv);
}